// round 1
// baseline (speedup 1.0000x reference)
#include <cuda_runtime.h>
#include <cstdint>

#define NB 16
#define NL 8192
#define ND 256
#define NH 4
#define DH 32
#define HID 128
#define QKV_LD 384

// ---------------- scratch (device globals; no allocation) ----------------
__device__ float g_kv[(size_t)NB * NL * 256];        // [b][l][0:128 expK | 128:256 V]  (128 MB)
__device__ float g_Sp[NB * NH * 32 * 1024];          // [b][h][split][d*32+e] partial S (8 MB)
__device__ float g_Zp[NB * NH * 32 * 32];            // [b][h][split][d]
__device__ float g_ctx[NB * NH * 32 * 32];           // [b][h][d][e]
__device__ float g_M[NB * HID * ND];                 // [b][hd][j]
__device__ float g_N[NB * ND * ND];                  // [b][i][j]

// ---------------- f32x2 helpers ----------------
typedef unsigned long long ull;

__device__ __forceinline__ ull pk2(float x, float y) {
    ull r; asm("mov.b64 %0, {%1,%2};" : "=l"(r) : "f"(x), "f"(y)); return r;
}
__device__ __forceinline__ ull fma2(ull a, ull b, ull c) {
    ull d; asm("fma.rn.f32x2 %0, %1, %2, %3;" : "=l"(d) : "l"(a), "l"(b), "l"(c)); return d;
}
__device__ __forceinline__ void upk2(ull v, float& a, float& b) {
    asm("mov.b64 {%0,%1}, %2;" : "=f"(a), "=f"(b) : "l"(v));
}

// ---------------- tiled f32x2 GEMM: C[bM x 128-tiles] = A @ B (+epilogue) ----------------
// BM=BN=128, BK=16, 256 threads, 8x8 per thread, accumulators packed f32x2.
__global__ void __launch_bounds__(256) gemm_f32x2(
    const float* __restrict__ A, int lda, long long sA,
    const float* __restrict__ B, int ldb, long long sB,
    float* __restrict__ C, int ldc, long long sC,
    int K, float scale, const float* __restrict__ bias, int exp_ncut)
{
    const int b = blockIdx.z;
    A += (size_t)b * sA + (size_t)blockIdx.y * 128 * lda;
    B += (size_t)b * sB;
    C += (size_t)b * sC + (size_t)blockIdx.y * 128 * ldc + blockIdx.x * 128;
    const int n0 = blockIdx.x * 128;

    __shared__ float As[16][128];
    __shared__ float Bs[16][128];

    const int tid = threadIdx.x;
    const int tx = tid & 15;
    const int ty = tid >> 4;

    ull acc[8][4];
#pragma unroll
    for (int m = 0; m < 8; m++)
#pragma unroll
        for (int p = 0; p < 4; p++) acc[m][p] = 0ULL;

    for (int k0 = 0; k0 < K; k0 += 16) {
        // A tile: 128x16 -> As[k][m] (transposed)
#pragma unroll
        for (int i = 0; i < 2; i++) {
            int f = tid + i * 256;
            int row = f >> 2, c4 = (f & 3) * 4;
            float4 av = *(const float4*)(A + (size_t)row * lda + k0 + c4);
            As[c4 + 0][row] = av.x; As[c4 + 1][row] = av.y;
            As[c4 + 2][row] = av.z; As[c4 + 3][row] = av.w;
        }
        // B tile: 16x128 -> Bs[k][n]
#pragma unroll
        for (int i = 0; i < 2; i++) {
            int f = tid + i * 256;
            int row = f >> 5, c = (f & 31) * 4;
            *(float4*)(&Bs[row][c]) = *(const float4*)(B + (size_t)(k0 + row) * ldb + n0 + c);
        }
        __syncthreads();

#pragma unroll
        for (int kk = 0; kk < 16; kk++) {
            float4 a0 = *(const float4*)(&As[kk][ty * 4]);
            float4 a1 = *(const float4*)(&As[kk][64 + ty * 4]);
            float4 b0 = *(const float4*)(&Bs[kk][tx * 4]);
            float4 b1 = *(const float4*)(&Bs[kk][64 + tx * 4]);
            ull bp[4] = { pk2(b0.x, b0.y), pk2(b0.z, b0.w),
                          pk2(b1.x, b1.y), pk2(b1.z, b1.w) };
            float am[8] = { a0.x, a0.y, a0.z, a0.w, a1.x, a1.y, a1.z, a1.w };
#pragma unroll
            for (int m = 0; m < 8; m++) {
                ull ap = pk2(am[m], am[m]);
#pragma unroll
                for (int p = 0; p < 4; p++) acc[m][p] = fma2(ap, bp[p], acc[m][p]);
            }
        }
        __syncthreads();
    }

    float4 bb0 = make_float4(0.f, 0.f, 0.f, 0.f), bb1 = bb0;
    if (bias) {
        bb0 = *(const float4*)(bias + n0 + tx * 4);
        bb1 = *(const float4*)(bias + n0 + 64 + tx * 4);
    }
    const bool doexp = (n0 < exp_ncut);   // tiles are 128-wide; exp_ncut is 0 or 128 -> uniform

#pragma unroll
    for (int m = 0; m < 8; m++) {
        int row = (m < 4) ? (ty * 4 + m) : (64 + ty * 4 + m - 4);
        float c0, c1, c2, c3, c4, c5, c6, c7;
        upk2(acc[m][0], c0, c1); upk2(acc[m][1], c2, c3);
        upk2(acc[m][2], c4, c5); upk2(acc[m][3], c6, c7);
        float4 o0 = make_float4(c0 * scale + bb0.x, c1 * scale + bb0.y,
                                c2 * scale + bb0.z, c3 * scale + bb0.w);
        float4 o1 = make_float4(c4 * scale + bb1.x, c5 * scale + bb1.y,
                                c6 * scale + bb1.z, c7 * scale + bb1.w);
        if (doexp) {
            o0.x = expf(o0.x); o0.y = expf(o0.y); o0.z = expf(o0.z); o0.w = expf(o0.w);
            o1.x = expf(o1.x); o1.y = expf(o1.y); o1.z = expf(o1.z); o1.w = expf(o1.w);
        }
        *(float4*)(C + (size_t)row * ldc + tx * 4) = o0;
        *(float4*)(C + (size_t)row * ldc + 64 + tx * 4) = o1;
    }
}

// ---------------- S = expK^T @ V partials, Z = sum expK  (per b,h,L-split) ----------------
__global__ void __launch_bounds__(64) reduce_kv()
{
    const int split = blockIdx.x;          // 32 splits of 256 rows
    const int h = blockIdx.y;              // 4
    const int b = blockIdx.z;              // 16
    const int t = threadIdx.x;             // 64
    const int di = t & 7, ej = t >> 3;

    const float* base = g_kv + ((size_t)b * NL + (size_t)split * 256) * 256;
    const float* kp = base + h * 32 + di * 4;
    const float* vp = base + 128 + h * 32 + ej * 4;

    float acc[4][4];
#pragma unroll
    for (int i = 0; i < 4; i++)
#pragma unroll
        for (int j = 0; j < 4; j++) acc[i][j] = 0.f;
    float z[4] = { 0.f, 0.f, 0.f, 0.f };

#pragma unroll 4
    for (int l = 0; l < 256; l++) {
        float4 kk = *(const float4*)(kp + (size_t)l * 256);
        float4 vv = *(const float4*)(vp + (size_t)l * 256);
        float ka[4] = { kk.x, kk.y, kk.z, kk.w };
        float va[4] = { vv.x, vv.y, vv.z, vv.w };
#pragma unroll
        for (int i = 0; i < 4; i++)
#pragma unroll
            for (int j = 0; j < 4; j++) acc[i][j] += ka[i] * va[j];
        if (ej == 0) {
#pragma unroll
            for (int i = 0; i < 4; i++) z[i] += ka[i];
        }
    }

    float* Sp = g_Sp + (((size_t)(b * 4 + h) * 32 + split) * 1024);
#pragma unroll
    for (int i = 0; i < 4; i++)
#pragma unroll
        for (int j = 0; j < 4; j++)
            Sp[(di * 4 + i) * 32 + ej * 4 + j] = acc[i][j];
    if (ej == 0) {
        float* Zp = g_Zp + ((size_t)(b * 4 + h) * 32 + split) * 32;
#pragma unroll
        for (int i = 0; i < 4; i++) Zp[di * 4 + i] = z[i];
    }
}

// ---------------- context = (sum_split S) / (sum_split Z) ----------------
__global__ void __launch_bounds__(1024) ctx_kernel()
{
    const int h = blockIdx.x, b = blockIdx.y;
    const int t = threadIdx.x;             // 1024 = d*32+e
    const int d = t >> 5, e = t & 31;

    const float* Sp = g_Sp + (size_t)(b * 4 + h) * 32 * 1024;
    float s = 0.f;
#pragma unroll
    for (int sp = 0; sp < 32; sp++) s += Sp[sp * 1024 + t];

    __shared__ float zs[32];
    if (e == 0) {
        const float* Zp = g_Zp + (size_t)(b * 4 + h) * 32 * 32;
        float zz = 0.f;
#pragma unroll
        for (int sp = 0; sp < 32; sp++) zz += Zp[sp * 32 + d];
        zs[d] = zz;
    }
    __syncthreads();
    g_ctx[(size_t)(b * 4 + h) * 1024 + t] = s / zs[d];
}

// ---------------- M[b][h*32+d][j] = sum_e ctx[h,d,e] * Wout[h*32+e][j] ----------------
__global__ void __launch_bounds__(256) m_kernel(const float* __restrict__ Wout)
{
    const int b = blockIdx.x;
    const int j = threadIdx.x;             // 256 columns
    __shared__ float cs[4096];
    for (int i = j; i < 4096; i += 256) cs[i] = g_ctx[(size_t)b * 4096 + i];
    __syncthreads();

    float* Mb = g_M + (size_t)b * HID * ND;
#pragma unroll
    for (int h = 0; h < 4; h++) {
        float w[32];
#pragma unroll
        for (int e = 0; e < 32; e++) w[e] = Wout[(h * 32 + e) * 256 + j];
        for (int d = 0; d < 32; d++) {
            float a = 0.f;
#pragma unroll
            for (int e = 0; e < 32; e++) a += cs[h * 1024 + d * 32 + e] * w[e];
            Mb[(h * 32 + d) * 256 + j] = a;
        }
    }
}

// ---------------- launch ----------------
extern "C" void kernel_launch(void* const* d_in, const int* in_sizes, int n_in,
                              void* d_out, int out_size)
{
    const float* x    = (const float*)d_in[0];   // [16,8192,256]
    const float* Wqkv = (const float*)d_in[1];   // [256,384]
    const float* Wout = (const float*)d_in[2];   // [128,256]
    const float* bout = (const float*)d_in[3];   // [256]
    float* out = (float*)d_out;

    float *kv, *Mp, *Np;
    cudaGetSymbolAddress((void**)&kv, g_kv);
    cudaGetSymbolAddress((void**)&Mp, g_M);
    cudaGetSymbolAddress((void**)&Np, g_N);

    const float scale = 0.17677669529663687f;    // 32^-0.5
    const long long sX = (long long)NL * ND;     // per-batch x stride

    // 1) kv = x @ Wqkv[:,128:384]; exp on first 128 cols
    gemm_f32x2<<<dim3(2, 64, NB), 256>>>(
        x, ND, sX,
        Wqkv + 128, QKV_LD, 0,
        kv, 256, (long long)NL * 256,
        ND, 1.0f, nullptr, 128);

    // 2) partial S, Z
    reduce_kv<<<dim3(32, NH, NB), 64>>>();

    // 3) context
    ctx_kernel<<<dim3(NH, NB), 1024>>>();

    // 4) M[b]
    m_kernel<<<NB, 256>>>(Wout);

    // 5) N[b] = scale * Wq @ M[b]
    gemm_f32x2<<<dim3(2, 2, NB), 256>>>(
        Wqkv, QKV_LD, 0,
        Mp, ND, (long long)HID * ND,
        Np, ND, (long long)ND * ND,
        HID, scale, nullptr, 0);

    // 6) out = x @ N[b] + b_out
    gemm_f32x2<<<dim3(2, 64, NB), 256>>>(
        x, ND, sX,
        Np, ND, (long long)ND * ND,
        out, ND, sX,
        ND, 1.0f, bout, 0);
}

// round 3
// speedup vs baseline: 1.3297x; 1.3297x over previous
#include <cuda_runtime.h>
#include <cuda_bf16.h>
#include <mma.h>
#include <cstdint>

using namespace nvcuda;

#define NB 16
#define NL 8192
#define ND 256
#define NH 4
#define HID 128
#define QKV_LD 384

typedef unsigned long long ull;
typedef unsigned int u32;

// ---------------- scratch (device globals; no allocation) ----------------
__device__ float g_kv[(size_t)NB * NL * 256];        // [b][l][0:128 expK | 128:256 V]
__device__ float g_Sp[NB * NH * 32 * 1024];          // partial S
__device__ float g_Zp[NB * NH * 32 * 32];            // partial Z
__device__ float g_ctx[NB * NH * 32 * 32];           // context
__device__ float g_M[NB * HID * ND];                 // M[b]
__device__ float g_N[NB * ND * ND];                  // N[b]
__device__ __nv_bfloat16 g_W1hi[256 * 256];          // Wkv^T hi  [n][k]
__device__ __nv_bfloat16 g_W1lo[256 * 256];
__device__ __nv_bfloat16 g_W3hi[NB * 256 * 256];     // N[b]^T hi [b][j][i]
__device__ __nv_bfloat16 g_W3lo[NB * 256 * 256];

// ---------------- smem helpers ----------------
__device__ __forceinline__ u32 smem_u32(const void* p) {
    u32 a;
    asm("{ .reg .u64 t; cvta.to.shared.u64 t, %1; cvt.u32.u64 %0, t; }" : "=r"(a) : "l"(p));
    return a;
}
__device__ __forceinline__ void sts128(u32 addr, u32 a, u32 b, u32 c, u32 d) {
    asm volatile("st.shared.v4.b32 [%0], {%1,%2,%3,%4};" :: "r"(addr), "r"(a), "r"(b), "r"(c), "r"(d) : "memory");
}
__device__ __forceinline__ u32 pack_bf2(float a, float b) {
    __nv_bfloat162 t = __floats2bfloat162_rn(a, b);
    return *reinterpret_cast<u32*>(&t);
}

// SMEM layout (bytes, bf16 stride 48 per row for 32-elem chunks)
#define S_AH 0
#define S_AL 12288
#define S_BH 24576
#define S_BL 49152
#define SMEM_DYN 131072   // union: stage buffers (73.7KB) / epilogue Cs (128KB)

// =====================================================================
// wmma bf16 split-3 GEMM: C[128-tile x 256] = A(f32) @ B^T, B pre-split [n][k] bf16
// mode 0: exp() on cols<128 (kv). mode 1: += bias (out).
// =====================================================================
__global__ void __launch_bounds__(256) mma_gemm(
    const float* __restrict__ A, long long sA,
    const __nv_bfloat16* __restrict__ Bhi, const __nv_bfloat16* __restrict__ Blo, long long sB,
    float* __restrict__ C, long long sC,
    const float* __restrict__ bias, int mode)
{
    extern __shared__ unsigned char smem_raw[];
    __nv_bfloat16* sm = reinterpret_cast<__nv_bfloat16*>(smem_raw);
    float* Cs = reinterpret_cast<float*>(smem_raw);
    const u32 sbase = smem_u32(smem_raw);

    const int tid = threadIdx.x;
    const int wid = tid >> 5;
    const int wm = wid >> 2;        // 0..1  (rows, 64 each)
    const int wn = wid & 3;         // 0..3  (cols, 64 each)
    const int b = blockIdx.y;
    const int l0 = blockIdx.x * 128;

    const float* Ab = A + (size_t)b * sA + (size_t)l0 * 256;
    const __nv_bfloat16* BhiB = Bhi + (size_t)b * sB;
    const __nv_bfloat16* BloB = Blo + (size_t)b * sB;

    wmma::fragment<wmma::accumulator, 16, 16, 16, float> acc[4][4];
#pragma unroll
    for (int mi = 0; mi < 4; mi++)
#pragma unroll
        for (int ni = 0; ni < 4; ni++) wmma::fill_fragment(acc[mi][ni], 0.0f);

    for (int k0 = 0; k0 < 256; k0 += 32) {
        // ---- A: 128 rows x 32 k, fp32 -> split bf16 hi/lo (each thread: 2x 8 floats)
#pragma unroll
        for (int i = 0; i < 2; i++) {
            int idx = tid + i * 256;          // 512 slots of 8 floats
            int row = idx >> 2, seg = idx & 3;
            const float* src = Ab + (size_t)row * 256 + k0 + seg * 8;
            float4 f0 = __ldg((const float4*)src);
            float4 f1 = __ldg((const float4*)(src + 4));
            float v[8] = { f0.x, f0.y, f0.z, f0.w, f1.x, f1.y, f1.z, f1.w };
            float h[8], l[8];
#pragma unroll
            for (int q = 0; q < 8; q++) {
                h[q] = __bfloat162float(__float2bfloat16(v[q]));
                l[q] = v[q] - h[q];
            }
            u32 off = (u32)(row * 96 + seg * 16);
            sts128(sbase + S_AH + off, pack_bf2(h[0], h[1]), pack_bf2(h[2], h[3]),
                                       pack_bf2(h[4], h[5]), pack_bf2(h[6], h[7]));
            sts128(sbase + S_AL + off, pack_bf2(l[0], l[1]), pack_bf2(l[2], l[3]),
                                       pack_bf2(l[4], l[5]), pack_bf2(l[6], l[7]));
        }
        // ---- B: 256 rows x 32 k bf16, hi+lo (each thread: 4x 8 bf16 per buffer)
#pragma unroll
        for (int i = 0; i < 4; i++) {
            int idx = tid + i * 256;          // 1024 slots of 8 bf16
            int n = idx >> 2, seg = idx & 3;
            size_t gofs = (size_t)n * 256 + k0 + seg * 8;
            uint4 vh = __ldg((const uint4*)(BhiB + gofs));
            uint4 vl = __ldg((const uint4*)(BloB + gofs));
            u32 off = (u32)(n * 96 + seg * 16);
            sts128(sbase + S_BH + off, vh.x, vh.y, vh.z, vh.w);
            sts128(sbase + S_BL + off, vl.x, vl.y, vl.z, vl.w);
        }
        __syncthreads();

        const __nv_bfloat16* Ah = sm;                     // [128][48]
        const __nv_bfloat16* Al = sm + 12288 / 2 * 1;     // byte 12288
        const __nv_bfloat16* Bh = sm + 24576 / 2;
        const __nv_bfloat16* Bl = sm + 49152 / 2;

#pragma unroll
        for (int kk = 0; kk < 2; kk++) {
            wmma::fragment<wmma::matrix_a, 16, 16, 16, __nv_bfloat16, wmma::row_major> ah[4], al[4];
            wmma::fragment<wmma::matrix_b, 16, 16, 16, __nv_bfloat16, wmma::col_major> bh[4], bl[4];
#pragma unroll
            for (int mi = 0; mi < 4; mi++) {
                int r = wm * 64 + mi * 16;
                wmma::load_matrix_sync(ah[mi], Ah + r * 48 + kk * 16, 48);
                wmma::load_matrix_sync(al[mi], Al + r * 48 + kk * 16, 48);
            }
#pragma unroll
            for (int ni = 0; ni < 4; ni++) {
                int n = wn * 64 + ni * 16;
                wmma::load_matrix_sync(bh[ni], Bh + n * 48 + kk * 16, 48);
                wmma::load_matrix_sync(bl[ni], Bl + n * 48 + kk * 16, 48);
            }
#pragma unroll
            for (int mi = 0; mi < 4; mi++)
#pragma unroll
                for (int ni = 0; ni < 4; ni++) {
                    wmma::mma_sync(acc[mi][ni], ah[mi], bh[ni], acc[mi][ni]);
                    wmma::mma_sync(acc[mi][ni], ah[mi], bl[ni], acc[mi][ni]);
                    wmma::mma_sync(acc[mi][ni], al[mi], bh[ni], acc[mi][ni]);
                }
        }
        __syncthreads();
    }

    // ---- epilogue: accs -> smem Cs[128][256] -> epilogue -> global
#pragma unroll
    for (int mi = 0; mi < 4; mi++)
#pragma unroll
        for (int ni = 0; ni < 4; ni++)
            wmma::store_matrix_sync(Cs + (size_t)(wm * 64 + mi * 16) * 256 + wn * 64 + ni * 16,
                                    acc[mi][ni], 256, wmma::mem_row_major);
    __syncthreads();

    float* Cb = C + (size_t)b * sC + (size_t)l0 * 256;
#pragma unroll
    for (int i = 0; i < 32; i++) {
        int idx = tid + i * 256;              // 8192 float4 slots
        int row = idx >> 6, c4 = idx & 63;
        float4 v = *(const float4*)(Cs + (size_t)row * 256 + c4 * 4);
        if (mode == 0) {
            if (c4 < 32) { v.x = expf(v.x); v.y = expf(v.y); v.z = expf(v.z); v.w = expf(v.w); }
        } else {
            float4 bb = __ldg((const float4*)(bias + c4 * 4));
            v.x += bb.x; v.y += bb.y; v.z += bb.z; v.w += bb.w;
        }
        *(float4*)(Cb + (size_t)row * 256 + c4 * 4) = v;
    }
}

// ---------------- prep: Wkv^T split ----------------
__global__ void prep_w1(const float* __restrict__ Wqkv)
{
    const int n = blockIdx.x, k = threadIdx.x;
    float w = Wqkv[k * QKV_LD + 128 + n];
    float h = __bfloat162float(__float2bfloat16(w));
    g_W1hi[n * 256 + k] = __float2bfloat16(h);
    g_W1lo[n * 256 + k] = __float2bfloat16(w - h);
}

// ---------------- prep: N[b]^T split (tiled transpose) ----------------
__global__ void tsplit()
{
    const int b = blockIdx.z;
    const int i0 = blockIdx.y * 32, j0 = blockIdx.x * 32;
    const int tx = threadIdx.x, ty = threadIdx.y;
    __shared__ float t[32][33];
    const float* Nb = g_N + (size_t)b * 65536;
#pragma unroll
    for (int r = ty; r < 32; r += 8)
        t[r][tx] = Nb[(size_t)(i0 + r) * 256 + j0 + tx];
    __syncthreads();
    __nv_bfloat16* Whi = g_W3hi + (size_t)b * 65536;
    __nv_bfloat16* Wlo = g_W3lo + (size_t)b * 65536;
#pragma unroll
    for (int r = ty; r < 32; r += 8) {
        float v = t[tx][r];
        float h = __bfloat162float(__float2bfloat16(v));
        Whi[(size_t)(j0 + r) * 256 + i0 + tx] = __float2bfloat16(h);
        Wlo[(size_t)(j0 + r) * 256 + i0 + tx] = __float2bfloat16(v - h);
    }
}

// ---------------- f32x2 helpers (small fp32 GEMM kept for N[b]) ----------------
__device__ __forceinline__ ull pk2(float x, float y) {
    ull r; asm("mov.b64 %0, {%1,%2};" : "=l"(r) : "f"(x), "f"(y)); return r;
}
__device__ __forceinline__ ull fma2(ull a, ull b, ull c) {
    ull d; asm("fma.rn.f32x2 %0, %1, %2, %3;" : "=l"(d) : "l"(a), "l"(b), "l"(c)); return d;
}
__device__ __forceinline__ void upk2(ull v, float& a, float& b) {
    asm("mov.b64 {%0,%1}, %2;" : "=f"(a), "=f"(b) : "l"(v));
}

__global__ void __launch_bounds__(256) gemm_f32x2(
    const float* __restrict__ A, int lda, long long sA,
    const float* __restrict__ B, int ldb, long long sB,
    float* __restrict__ C, int ldc, long long sC,
    int K, float scale)
{
    const int b = blockIdx.z;
    A += (size_t)b * sA + (size_t)blockIdx.y * 128 * lda;
    B += (size_t)b * sB;
    C += (size_t)b * sC + (size_t)blockIdx.y * 128 * ldc + blockIdx.x * 128;
    const int n0 = blockIdx.x * 128;

    __shared__ float As[16][128];
    __shared__ float Bs[16][128];
    const int tid = threadIdx.x;
    const int tx = tid & 15;
    const int ty = tid >> 4;

    ull acc[8][4];
#pragma unroll
    for (int m = 0; m < 8; m++)
#pragma unroll
        for (int p = 0; p < 4; p++) acc[m][p] = 0ULL;

    for (int k0 = 0; k0 < K; k0 += 16) {
#pragma unroll
        for (int i = 0; i < 2; i++) {
            int f = tid + i * 256;
            int row = f >> 2, c4 = (f & 3) * 4;
            float4 av = *(const float4*)(A + (size_t)row * lda + k0 + c4);
            As[c4 + 0][row] = av.x; As[c4 + 1][row] = av.y;
            As[c4 + 2][row] = av.z; As[c4 + 3][row] = av.w;
        }
#pragma unroll
        for (int i = 0; i < 2; i++) {
            int f = tid + i * 256;
            int row = f >> 5, c = (f & 31) * 4;
            *(float4*)(&Bs[row][c]) = *(const float4*)(B + (size_t)(k0 + row) * ldb + n0 + c);
        }
        __syncthreads();
#pragma unroll
        for (int kk = 0; kk < 16; kk++) {
            float4 a0 = *(const float4*)(&As[kk][ty * 4]);
            float4 a1 = *(const float4*)(&As[kk][64 + ty * 4]);
            float4 b0 = *(const float4*)(&Bs[kk][tx * 4]);
            float4 b1 = *(const float4*)(&Bs[kk][64 + tx * 4]);
            ull bp[4] = { pk2(b0.x, b0.y), pk2(b0.z, b0.w), pk2(b1.x, b1.y), pk2(b1.z, b1.w) };
            float am[8] = { a0.x, a0.y, a0.z, a0.w, a1.x, a1.y, a1.z, a1.w };
#pragma unroll
            for (int m = 0; m < 8; m++) {
                ull ap = pk2(am[m], am[m]);
#pragma unroll
                for (int p = 0; p < 4; p++) acc[m][p] = fma2(ap, bp[p], acc[m][p]);
            }
        }
        __syncthreads();
    }

#pragma unroll
    for (int m = 0; m < 8; m++) {
        int row = (m < 4) ? (ty * 4 + m) : (64 + ty * 4 + m - 4);
        float c0, c1, c2, c3, c4, c5, c6, c7;
        upk2(acc[m][0], c0, c1); upk2(acc[m][1], c2, c3);
        upk2(acc[m][2], c4, c5); upk2(acc[m][3], c6, c7);
        *(float4*)(C + (size_t)row * ldc + tx * 4) =
            make_float4(c0 * scale, c1 * scale, c2 * scale, c3 * scale);
        *(float4*)(C + (size_t)row * ldc + 64 + tx * 4) =
            make_float4(c4 * scale, c5 * scale, c6 * scale, c7 * scale);
    }
}

// ---------------- S = expK^T @ V partials, Z ----------------
__global__ void __launch_bounds__(64) reduce_kv()
{
    const int split = blockIdx.x;
    const int h = blockIdx.y;
    const int b = blockIdx.z;
    const int t = threadIdx.x;
    const int di = t & 7, ej = t >> 3;

    const float* base = g_kv + ((size_t)b * NL + (size_t)split * 256) * 256;
    const float* kp = base + h * 32 + di * 4;
    const float* vp = base + 128 + h * 32 + ej * 4;

    float acc[4][4];
#pragma unroll
    for (int i = 0; i < 4; i++)
#pragma unroll
        for (int j = 0; j < 4; j++) acc[i][j] = 0.f;
    float z[4] = { 0.f, 0.f, 0.f, 0.f };

#pragma unroll 4
    for (int l = 0; l < 256; l++) {
        float4 kk = *(const float4*)(kp + (size_t)l * 256);
        float4 vv = *(const float4*)(vp + (size_t)l * 256);
        float ka[4] = { kk.x, kk.y, kk.z, kk.w };
        float va[4] = { vv.x, vv.y, vv.z, vv.w };
#pragma unroll
        for (int i = 0; i < 4; i++)
#pragma unroll
            for (int j = 0; j < 4; j++) acc[i][j] += ka[i] * va[j];
        if (ej == 0) {
#pragma unroll
            for (int i = 0; i < 4; i++) z[i] += ka[i];
        }
    }
    float* Sp = g_Sp + (((size_t)(b * 4 + h) * 32 + split) * 1024);
#pragma unroll
    for (int i = 0; i < 4; i++)
#pragma unroll
        for (int j = 0; j < 4; j++)
            Sp[(di * 4 + i) * 32 + ej * 4 + j] = acc[i][j];
    if (ej == 0) {
        float* Zp = g_Zp + ((size_t)(b * 4 + h) * 32 + split) * 32;
#pragma unroll
        for (int i = 0; i < 4; i++) Zp[di * 4 + i] = z[i];
    }
}

// ---------------- context ----------------
__global__ void __launch_bounds__(1024) ctx_kernel()
{
    const int h = blockIdx.x, b = blockIdx.y;
    const int t = threadIdx.x;
    const int d = t >> 5, e = t & 31;
    const float* Sp = g_Sp + (size_t)(b * 4 + h) * 32 * 1024;
    float s = 0.f;
#pragma unroll
    for (int sp = 0; sp < 32; sp++) s += Sp[sp * 1024 + t];
    __shared__ float zs[32];
    if (e == 0) {
        const float* Zp = g_Zp + (size_t)(b * 4 + h) * 32 * 32;
        float zz = 0.f;
#pragma unroll
        for (int sp = 0; sp < 32; sp++) zz += Zp[sp * 32 + d];
        zs[d] = zz;
    }
    __syncthreads();
    g_ctx[(size_t)(b * 4 + h) * 1024 + t] = s / zs[d];
}

// ---------------- M[b] ----------------
__global__ void __launch_bounds__(256) m_kernel(const float* __restrict__ Wout)
{
    const int b = blockIdx.x;
    const int h = blockIdx.y;
    const int j = threadIdx.x;
    __shared__ float cs[1024];
    for (int i = j; i < 1024; i += 256) cs[i] = g_ctx[(size_t)b * 4096 + h * 1024 + i];
    __syncthreads();
    float* Mb = g_M + (size_t)b * HID * ND;
    float w[32];
#pragma unroll
    for (int e = 0; e < 32; e++) w[e] = Wout[(h * 32 + e) * 256 + j];
    for (int d = 0; d < 32; d++) {
        float a = 0.f;
#pragma unroll
        for (int e = 0; e < 32; e++) a += cs[d * 32 + e] * w[e];
        Mb[(h * 32 + d) * 256 + j] = a;
    }
}

// ---------------- launch ----------------
extern "C" void kernel_launch(void* const* d_in, const int* in_sizes, int n_in,
                              void* d_out, int out_size)
{
    const float* x    = (const float*)d_in[0];
    const float* Wqkv = (const float*)d_in[1];
    const float* Wout = (const float*)d_in[2];
    const float* bout = (const float*)d_in[3];
    float* out = (float*)d_out;

    float *kv, *Mp, *Np;
    __nv_bfloat16 *w1h, *w1l, *w3h, *w3l;
    cudaGetSymbolAddress((void**)&kv, g_kv);
    cudaGetSymbolAddress((void**)&Mp, g_M);
    cudaGetSymbolAddress((void**)&Np, g_N);
    cudaGetSymbolAddress((void**)&w1h, g_W1hi);
    cudaGetSymbolAddress((void**)&w1l, g_W1lo);
    cudaGetSymbolAddress((void**)&w3h, g_W3hi);
    cudaGetSymbolAddress((void**)&w3l, g_W3lo);

    cudaFuncSetAttribute(mma_gemm, cudaFuncAttributeMaxDynamicSharedMemorySize, SMEM_DYN);

    const float scale = 0.17677669529663687f;
    const long long sX = (long long)NL * ND;

    // 1) split Wkv^T
    prep_w1<<<256, 256>>>(Wqkv);

    // 2) kv = x @ Wkv (wmma bf16 split-3, exp on first 128 cols)
    mma_gemm<<<dim3(64, NB), 256, SMEM_DYN>>>(
        x, sX, w1h, w1l, 0, kv, (long long)NL * 256, nullptr, 0);

    // 3) partial S, Z
    reduce_kv<<<dim3(32, NH, NB), 64>>>();

    // 4) context
    ctx_kernel<<<dim3(NH, NB), 1024>>>();

    // 5) M[b]
    m_kernel<<<dim3(NB, NH), 256>>>(Wout);

    // 6) N[b] = scale * Wq @ M[b] (small fp32 GEMM)
    gemm_f32x2<<<dim3(2, 2, NB), 256>>>(
        Wqkv, QKV_LD, 0, Mp, ND, (long long)HID * ND,
        Np, ND, (long long)ND * ND, HID, scale);

    // 7) transpose+split N[b]
    tsplit<<<dim3(8, 8, NB), dim3(32, 8)>>>();

    // 8) out = x @ N[b] + b_out (wmma bf16 split-3)
    mma_gemm<<<dim3(64, NB), 256, SMEM_DYN>>>(
        x, sX, w3h, w3l, 65536, out, sX, bout, 1);
}

// round 4
// speedup vs baseline: 1.5679x; 1.1792x over previous
#include <cuda_runtime.h>
#include <cuda_bf16.h>
#include <mma.h>
#include <cstdint>

using namespace nvcuda;

#define NB 16
#define NL 8192
#define ND 256
#define NH 4
#define HID 128
#define QKV_LD 384

typedef unsigned long long ull;
typedef unsigned int u32;

// ---------------- scratch (device globals; no allocation) ----------------
__device__ __nv_bfloat16 g_Xhi[(size_t)NB * NL * 256];   // x split hi (64MB)
__device__ __nv_bfloat16 g_Xlo[(size_t)NB * NL * 256];   // x split lo (64MB)
__device__ float g_Sp[(size_t)NB * NH * 64 * 1024];      // per-CTA partial S (16MB)
__device__ float g_Zp[NB * NH * 64 * 32];                // per-CTA partial Z
__device__ float g_ctx[NB * NH * 32 * 32];               // context
__device__ float g_M[NB * HID * ND];                     // M[b]
__device__ float g_N[NB * ND * ND];                      // N[b]
__device__ __nv_bfloat16 g_W1hi[256 * 256];              // Wkv^T hi  [n][k]
__device__ __nv_bfloat16 g_W1lo[256 * 256];
__device__ __nv_bfloat16 g_W3hi[NB * 256 * 256];         // N[b]^T hi [b][j][i]
__device__ __nv_bfloat16 g_W3lo[NB * 256 * 256];

// ---------------- helpers ----------------
__device__ __forceinline__ u32 smem_u32(const void* p) {
    u32 a;
    asm("{ .reg .u64 t; cvta.to.shared.u64 t, %1; cvt.u32.u64 %0, t; }" : "=r"(a) : "l"(p));
    return a;
}
__device__ __forceinline__ void cp16(u32 dst, const void* src) {
    asm volatile("cp.async.cg.shared.global [%0], [%1], 16;" :: "r"(dst), "l"(src) : "memory");
}
__device__ __forceinline__ void cp_commit() { asm volatile("cp.async.commit_group;" ::: "memory"); }
template<int N> __device__ __forceinline__ void cp_wait() {
    asm volatile("cp.async.wait_group %0;" :: "n"(N) : "memory");
}
__device__ __forceinline__ ull pk2(float x, float y) {
    ull r; asm("mov.b64 %0, {%1,%2};" : "=l"(r) : "f"(x), "f"(y)); return r;
}
__device__ __forceinline__ ull fma2(ull a, ull b, ull c) {
    ull d; asm("fma.rn.f32x2 %0, %1, %2, %3;" : "=l"(d) : "l"(a), "l"(b), "l"(c)); return d;
}
__device__ __forceinline__ ull add2(ull a, ull b) {
    ull d; asm("add.rn.f32x2 %0, %1, %2;" : "=l"(d) : "l"(a), "l"(b)); return d;
}
__device__ __forceinline__ void upk2(ull v, float& a, float& b) {
    asm("mov.b64 {%0,%1}, %2;" : "=f"(a), "=f"(b) : "l"(v));
}

// SMEM stage layout (bytes from dynamic base). 48-bf16 (96B) row stride.
#define SZ_A 12288
#define SZ_B 24576
#define O_AH 0
#define O_AL 24576
#define O_BH 49152
#define O_BL 98304
#define SMEM_DYN 147456   // stages (144KB) union epilogue Cs (128KB)

// =====================================================================
// wmma bf16 split-3 GEMM, cp.async double-buffered.
// C[128-tile x 256] = A @ B^T ; A = pre-split x (hi/lo bf16), B pre-split [n][k].
// mode 0: epilogue computes exp + per-CTA partial S,Z (no C write).
// mode 1: epilogue adds bias, writes C.
// =====================================================================
__global__ void __launch_bounds__(256) mma_gemm(
    const __nv_bfloat16* __restrict__ Ahi, const __nv_bfloat16* __restrict__ Alo, long long sA,
    const __nv_bfloat16* __restrict__ Bhi, const __nv_bfloat16* __restrict__ Blo, long long sB,
    float* __restrict__ C, long long sC,
    const float* __restrict__ bias, int mode)
{
    extern __shared__ unsigned char smem_raw[];
    __nv_bfloat16* sm = reinterpret_cast<__nv_bfloat16*>(smem_raw);
    float* Cs = reinterpret_cast<float*>(smem_raw);
    const u32 sbase = smem_u32(smem_raw);

    const int tid = threadIdx.x;
    const int wid = tid >> 5;
    const int wm = wid >> 2;        // 0..1
    const int wn = wid & 3;         // 0..3
    const int b = blockIdx.y;
    const int l0 = blockIdx.x * 128;

    const __nv_bfloat16* AhiB = Ahi + (size_t)b * sA + (size_t)l0 * 256;
    const __nv_bfloat16* AloB = Alo + (size_t)b * sA + (size_t)l0 * 256;
    const __nv_bfloat16* BhiB = Bhi + (size_t)b * sB;
    const __nv_bfloat16* BloB = Blo + (size_t)b * sB;

    wmma::fragment<wmma::accumulator, 16, 16, 16, float> acc[4][4];
#pragma unroll
    for (int mi = 0; mi < 4; mi++)
#pragma unroll
        for (int ni = 0; ni < 4; ni++) wmma::fill_fragment(acc[mi][ni], 0.0f);

    auto issue_chunk = [&](int it, int st) {
        const int k0 = it * 32;
        const u32 aH = sbase + O_AH + st * SZ_A;
        const u32 aL = sbase + O_AL + st * SZ_A;
        const u32 bH = sbase + O_BH + st * SZ_B;
        const u32 bL = sbase + O_BL + st * SZ_B;
#pragma unroll
        for (int i = 0; i < 2; i++) {                  // A: 512 16B ops each
            int idx = tid + i * 256;
            int row = idx >> 2, seg = idx & 3;
            size_t go = (size_t)row * 256 + k0 + seg * 8;
            u32 so = (u32)(row * 96 + seg * 16);
            cp16(aH + so, AhiB + go);
            cp16(aL + so, AloB + go);
        }
#pragma unroll
        for (int i = 0; i < 4; i++) {                  // B: 1024 16B ops each
            int idx = tid + i * 256;
            int n = idx >> 2, seg = idx & 3;
            size_t go = (size_t)n * 256 + k0 + seg * 8;
            u32 so = (u32)(n * 96 + seg * 16);
            cp16(bH + so, BhiB + go);
            cp16(bL + so, BloB + go);
        }
        cp_commit();
    };

    issue_chunk(0, 0);

    for (int it = 0; it < 8; it++) {
        const int st = it & 1;
        if (it < 7) issue_chunk(it + 1, st ^ 1);
        if (it < 7) cp_wait<1>(); else cp_wait<0>();
        __syncthreads();

        const __nv_bfloat16* Ah = (const __nv_bfloat16*)(smem_raw + O_AH + st * SZ_A);
        const __nv_bfloat16* Al = (const __nv_bfloat16*)(smem_raw + O_AL + st * SZ_A);
        const __nv_bfloat16* Bh = (const __nv_bfloat16*)(smem_raw + O_BH + st * SZ_B);
        const __nv_bfloat16* Bl = (const __nv_bfloat16*)(smem_raw + O_BL + st * SZ_B);

#pragma unroll
        for (int kk = 0; kk < 2; kk++) {
            wmma::fragment<wmma::matrix_a, 16, 16, 16, __nv_bfloat16, wmma::row_major> ah[4], al[4];
            wmma::fragment<wmma::matrix_b, 16, 16, 16, __nv_bfloat16, wmma::col_major> bh[4], bl[4];
#pragma unroll
            for (int mi = 0; mi < 4; mi++) {
                int r = wm * 64 + mi * 16;
                wmma::load_matrix_sync(ah[mi], Ah + r * 48 + kk * 16, 48);
                wmma::load_matrix_sync(al[mi], Al + r * 48 + kk * 16, 48);
            }
#pragma unroll
            for (int ni = 0; ni < 4; ni++) {
                int n = wn * 64 + ni * 16;
                wmma::load_matrix_sync(bh[ni], Bh + n * 48 + kk * 16, 48);
                wmma::load_matrix_sync(bl[ni], Bl + n * 48 + kk * 16, 48);
            }
#pragma unroll
            for (int mi = 0; mi < 4; mi++)
#pragma unroll
                for (int ni = 0; ni < 4; ni++) {
                    wmma::mma_sync(acc[mi][ni], ah[mi], bh[ni], acc[mi][ni]);
                    wmma::mma_sync(acc[mi][ni], ah[mi], bl[ni], acc[mi][ni]);
                    wmma::mma_sync(acc[mi][ni], al[mi], bh[ni], acc[mi][ni]);
                }
        }
        __syncthreads();
    }

    // ---- stage buffers dead; alias Cs[128][256] over them
#pragma unroll
    for (int mi = 0; mi < 4; mi++)
#pragma unroll
        for (int ni = 0; ni < 4; ni++)
            wmma::store_matrix_sync(Cs + (size_t)(wm * 64 + mi * 16) * 256 + wn * 64 + ni * 16,
                                    acc[mi][ni], 256, wmma::mem_row_major);
    __syncthreads();

    if (mode == 1) {
        float* Cb = C + (size_t)b * sC + (size_t)l0 * 256;
#pragma unroll
        for (int i = 0; i < 32; i++) {
            int idx = tid + i * 256;
            int row = idx >> 6, c4 = idx & 63;
            float4 v = *(const float4*)(Cs + (size_t)row * 256 + c4 * 4);
            float4 bb = __ldg((const float4*)(bias + c4 * 4));
            v.x += bb.x; v.y += bb.y; v.z += bb.z; v.w += bb.w;
            *(float4*)(Cb + (size_t)row * 256 + c4 * 4) = v;
        }
        return;
    }

    // ---- mode 0: exp in-place on K half (cols 0..127)
#pragma unroll
    for (int i = 0; i < 16; i++) {
        int idx = tid + i * 256;                  // 4096 float4 slots over 128x128
        int row = idx >> 5, c4 = idx & 31;
        float4 v = *(const float4*)(Cs + (size_t)row * 256 + c4 * 4);
        v.x = expf(v.x); v.y = expf(v.y); v.z = expf(v.z); v.w = expf(v.w);
        *(float4*)(Cs + (size_t)row * 256 + c4 * 4) = v;
    }
    __syncthreads();

    // ---- per-CTA partial S[h][d][e] (fp32, f32x2 packed) + Z[h][d]
    {
        const int h = tid >> 6;
        const int q = tid & 63;
        const int d0 = (q >> 3) * 4;
        const int e0 = (q & 7) * 4;
        ull acc2[4][2];
#pragma unroll
        for (int i = 0; i < 4; i++) { acc2[i][0] = 0ULL; acc2[i][1] = 0ULL; }
        ull z01 = 0ULL, z23 = 0ULL;

#pragma unroll 4
        for (int l = 0; l < 128; l++) {
            float4 ek = *(const float4*)(Cs + (size_t)l * 256 + h * 32 + d0);
            float4 vv = *(const float4*)(Cs + (size_t)l * 256 + 128 + h * 32 + e0);
            ull v01 = pk2(vv.x, vv.y), v23 = pk2(vv.z, vv.w);
            float ea[4] = { ek.x, ek.y, ek.z, ek.w };
#pragma unroll
            for (int i = 0; i < 4; i++) {
                ull ap = pk2(ea[i], ea[i]);
                acc2[i][0] = fma2(ap, v01, acc2[i][0]);
                acc2[i][1] = fma2(ap, v23, acc2[i][1]);
            }
            z01 = add2(z01, pk2(ek.x, ek.y));
            z23 = add2(z23, pk2(ek.z, ek.w));
        }

        float* Sp = g_Sp + (((size_t)(b * 4 + h) * 64 + blockIdx.x) * 1024);
#pragma unroll
        for (int i = 0; i < 4; i++) {
            float s0, s1, s2, s3;
            upk2(acc2[i][0], s0, s1); upk2(acc2[i][1], s2, s3);
            *(float4*)(Sp + (d0 + i) * 32 + e0) = make_float4(s0, s1, s2, s3);
        }
        if (e0 == 0) {
            float z0, z1, z2, z3;
            upk2(z01, z0, z1); upk2(z23, z2, z3);
            float* Zp = g_Zp + ((size_t)(b * 4 + h) * 64 + blockIdx.x) * 32;
            *(float4*)(Zp + d0) = make_float4(z0, z1, z2, z3);
        }
    }
}

// ---------------- split x: fp32 -> bf16 hi/lo ----------------
__global__ void __launch_bounds__(256) split_x(const float* __restrict__ x)
{
    size_t i4 = (size_t)blockIdx.x * 256 + threadIdx.x;   // 8388608 float4 groups
    float4 v = __ldg((const float4*)x + i4);
    float h0 = __bfloat162float(__float2bfloat16(v.x));
    float h1 = __bfloat162float(__float2bfloat16(v.y));
    float h2 = __bfloat162float(__float2bfloat16(v.z));
    float h3 = __bfloat162float(__float2bfloat16(v.w));
    __nv_bfloat162 hi0 = __floats2bfloat162_rn(h0, h1);
    __nv_bfloat162 hi1 = __floats2bfloat162_rn(h2, h3);
    __nv_bfloat162 lo0 = __floats2bfloat162_rn(v.x - h0, v.y - h1);
    __nv_bfloat162 lo1 = __floats2bfloat162_rn(v.z - h2, v.w - h3);
    *(uint2*)(g_Xhi + i4 * 4) = make_uint2(*(u32*)&hi0, *(u32*)&hi1);
    *(uint2*)(g_Xlo + i4 * 4) = make_uint2(*(u32*)&lo0, *(u32*)&lo1);
}

// ---------------- prep: Wkv^T split ----------------
__global__ void prep_w1(const float* __restrict__ Wqkv)
{
    const int n = blockIdx.x, k = threadIdx.x;
    float w = Wqkv[k * QKV_LD + 128 + n];
    float h = __bfloat162float(__float2bfloat16(w));
    g_W1hi[n * 256 + k] = __float2bfloat16(h);
    g_W1lo[n * 256 + k] = __float2bfloat16(w - h);
}

// ---------------- prep: N[b]^T split (tiled transpose) ----------------
__global__ void tsplit()
{
    const int b = blockIdx.z;
    const int i0 = blockIdx.y * 32, j0 = blockIdx.x * 32;
    const int tx = threadIdx.x, ty = threadIdx.y;
    __shared__ float t[32][33];
    const float* Nb = g_N + (size_t)b * 65536;
#pragma unroll
    for (int r = ty; r < 32; r += 8)
        t[r][tx] = Nb[(size_t)(i0 + r) * 256 + j0 + tx];
    __syncthreads();
    __nv_bfloat16* Whi = g_W3hi + (size_t)b * 65536;
    __nv_bfloat16* Wlo = g_W3lo + (size_t)b * 65536;
#pragma unroll
    for (int r = ty; r < 32; r += 8) {
        float v = t[tx][r];
        float h = __bfloat162float(__float2bfloat16(v));
        Whi[(size_t)(j0 + r) * 256 + i0 + tx] = __float2bfloat16(h);
        Wlo[(size_t)(j0 + r) * 256 + i0 + tx] = __float2bfloat16(v - h);
    }
}

// ---------------- small fp32 GEMM (N[b] = scale * Wq @ M[b]) ----------------
__global__ void __launch_bounds__(256) gemm_f32x2(
    const float* __restrict__ A, int lda, long long sA,
    const float* __restrict__ B, int ldb, long long sB,
    float* __restrict__ C, int ldc, long long sC,
    int K, float scale)
{
    const int b = blockIdx.z;
    A += (size_t)b * sA + (size_t)blockIdx.y * 128 * lda;
    B += (size_t)b * sB;
    C += (size_t)b * sC + (size_t)blockIdx.y * 128 * ldc + blockIdx.x * 128;
    const int n0 = blockIdx.x * 128;

    __shared__ float As[16][128];
    __shared__ float Bs[16][128];
    const int tid = threadIdx.x;
    const int tx = tid & 15;
    const int ty = tid >> 4;

    ull acc[8][4];
#pragma unroll
    for (int m = 0; m < 8; m++)
#pragma unroll
        for (int p = 0; p < 4; p++) acc[m][p] = 0ULL;

    for (int k0 = 0; k0 < K; k0 += 16) {
#pragma unroll
        for (int i = 0; i < 2; i++) {
            int f = tid + i * 256;
            int row = f >> 2, c4 = (f & 3) * 4;
            float4 av = *(const float4*)(A + (size_t)row * lda + k0 + c4);
            As[c4 + 0][row] = av.x; As[c4 + 1][row] = av.y;
            As[c4 + 2][row] = av.z; As[c4 + 3][row] = av.w;
        }
#pragma unroll
        for (int i = 0; i < 2; i++) {
            int f = tid + i * 256;
            int row = f >> 5, c = (f & 31) * 4;
            *(float4*)(&Bs[row][c]) = *(const float4*)(B + (size_t)(k0 + row) * ldb + n0 + c);
        }
        __syncthreads();
#pragma unroll
        for (int kk = 0; kk < 16; kk++) {
            float4 a0 = *(const float4*)(&As[kk][ty * 4]);
            float4 a1 = *(const float4*)(&As[kk][64 + ty * 4]);
            float4 b0 = *(const float4*)(&Bs[kk][tx * 4]);
            float4 b1 = *(const float4*)(&Bs[kk][64 + tx * 4]);
            ull bp[4] = { pk2(b0.x, b0.y), pk2(b0.z, b0.w), pk2(b1.x, b1.y), pk2(b1.z, b1.w) };
            float am[8] = { a0.x, a0.y, a0.z, a0.w, a1.x, a1.y, a1.z, a1.w };
#pragma unroll
            for (int m = 0; m < 8; m++) {
                ull ap = pk2(am[m], am[m]);
#pragma unroll
                for (int p = 0; p < 4; p++) acc[m][p] = fma2(ap, bp[p], acc[m][p]);
            }
        }
        __syncthreads();
    }

#pragma unroll
    for (int m = 0; m < 8; m++) {
        int row = (m < 4) ? (ty * 4 + m) : (64 + ty * 4 + m - 4);
        float c0, c1, c2, c3, c4, c5, c6, c7;
        upk2(acc[m][0], c0, c1); upk2(acc[m][1], c2, c3);
        upk2(acc[m][2], c4, c5); upk2(acc[m][3], c6, c7);
        *(float4*)(C + (size_t)row * ldc + tx * 4) =
            make_float4(c0 * scale, c1 * scale, c2 * scale, c3 * scale);
        *(float4*)(C + (size_t)row * ldc + 64 + tx * 4) =
            make_float4(c4 * scale, c5 * scale, c6 * scale, c7 * scale);
    }
}

// ---------------- context = (sum_cta S) / (sum_cta Z) ----------------
__global__ void __launch_bounds__(1024) ctx_kernel()
{
    const int h = blockIdx.x, b = blockIdx.y;
    const int t = threadIdx.x;
    const int d = t >> 5, e = t & 31;
    const float* Sp = g_Sp + (size_t)(b * 4 + h) * 64 * 1024;
    float s = 0.f;
#pragma unroll
    for (int sp = 0; sp < 64; sp++) s += Sp[sp * 1024 + t];
    __shared__ float zs[32];
    if (e == 0) {
        const float* Zp = g_Zp + (size_t)(b * 4 + h) * 64 * 32;
        float zz = 0.f;
#pragma unroll
        for (int sp = 0; sp < 64; sp++) zz += Zp[sp * 32 + d];
        zs[d] = zz;
    }
    __syncthreads();
    g_ctx[(size_t)(b * 4 + h) * 1024 + t] = s / zs[d];
}

// ---------------- M[b] ----------------
__global__ void __launch_bounds__(256) m_kernel(const float* __restrict__ Wout)
{
    const int b = blockIdx.x;
    const int h = blockIdx.y;
    const int j = threadIdx.x;
    __shared__ float cs[1024];
    for (int i = j; i < 1024; i += 256) cs[i] = g_ctx[(size_t)b * 4096 + h * 1024 + i];
    __syncthreads();
    float* Mb = g_M + (size_t)b * HID * ND;
    float w[32];
#pragma unroll
    for (int e = 0; e < 32; e++) w[e] = Wout[(h * 32 + e) * 256 + j];
    for (int d = 0; d < 32; d++) {
        float a = 0.f;
#pragma unroll
        for (int e = 0; e < 32; e++) a += cs[d * 32 + e] * w[e];
        Mb[(h * 32 + d) * 256 + j] = a;
    }
}

// ---------------- launch ----------------
extern "C" void kernel_launch(void* const* d_in, const int* in_sizes, int n_in,
                              void* d_out, int out_size)
{
    const float* x    = (const float*)d_in[0];
    const float* Wqkv = (const float*)d_in[1];
    const float* Wout = (const float*)d_in[2];
    const float* bout = (const float*)d_in[3];
    float* out = (float*)d_out;

    float *Mp, *Np;
    __nv_bfloat16 *xh, *xl, *w1h, *w1l, *w3h, *w3l;
    cudaGetSymbolAddress((void**)&Mp, g_M);
    cudaGetSymbolAddress((void**)&Np, g_N);
    cudaGetSymbolAddress((void**)&xh, g_Xhi);
    cudaGetSymbolAddress((void**)&xl, g_Xlo);
    cudaGetSymbolAddress((void**)&w1h, g_W1hi);
    cudaGetSymbolAddress((void**)&w1l, g_W1lo);
    cudaGetSymbolAddress((void**)&w3h, g_W3hi);
    cudaGetSymbolAddress((void**)&w3l, g_W3lo);

    cudaFuncSetAttribute(mma_gemm, cudaFuncAttributeMaxDynamicSharedMemorySize, SMEM_DYN);

    const float scale = 0.17677669529663687f;
    const long long sX = (long long)NL * ND;

    // 1) split x -> bf16 hi/lo  (33.55M elems / 4 per thread)
    split_x<<<32768, 256>>>(x);

    // 2) split Wkv^T
    prep_w1<<<256, 256>>>(Wqkv);

    // 3) kv GEMM + fused exp + partial S,Z (no kv materialization)
    mma_gemm<<<dim3(64, NB), 256, SMEM_DYN>>>(
        xh, xl, sX, w1h, w1l, 0, nullptr, 0, nullptr, 0);

    // 4) context
    ctx_kernel<<<dim3(NH, NB), 1024>>>();

    // 5) M[b]
    m_kernel<<<dim3(NB, NH), 256>>>(Wout);

    // 6) N[b] = scale * Wq @ M[b]
    gemm_f32x2<<<dim3(2, 2, NB), 256>>>(
        Wqkv, QKV_LD, 0, Mp, ND, (long long)HID * ND,
        Np, ND, (long long)ND * ND, HID, scale);

    // 7) transpose+split N[b]
    tsplit<<<dim3(8, 8, NB), dim3(32, 8)>>>();

    // 8) out = x @ N[b] + b_out
    mma_gemm<<<dim3(64, NB), 256, SMEM_DYN>>>(
        xh, xl, sX, w3h, w3l, 65536, out, sX, bout, 1);
}

// round 5
// speedup vs baseline: 1.7741x; 1.1315x over previous
#include <cuda_runtime.h>
#include <cuda_bf16.h>
#include <mma.h>
#include <cstdint>

using namespace nvcuda;

#define NB 16
#define NL 8192
#define ND 256
#define NH 4
#define HID 128
#define QKV_LD 384

typedef unsigned long long ull;
typedef unsigned int u32;

// ---------------- scratch (device globals; no allocation) ----------------
__device__ __nv_bfloat16 g_Xhi[(size_t)NB * NL * 256];   // x split hi (64MB)
__device__ __nv_bfloat16 g_Xlo[(size_t)NB * NL * 256];   // x split lo (64MB)
__device__ float g_Sp[(size_t)NB * NH * 64 * 1024];      // per-CTA partial S (16MB)
__device__ float g_Zp[NB * NH * 64 * 32];                // per-CTA partial Z
__device__ float g_ctx[NB * NH * 32 * 32];               // context
__device__ float g_M[NB * HID * ND];                     // M[b]
__device__ float g_N[NB * ND * ND];                      // N[b]
__device__ __nv_bfloat16 g_W1hi[256 * 256];              // Wkv^T hi  [n][k]
__device__ __nv_bfloat16 g_W1lo[256 * 256];
__device__ __nv_bfloat16 g_W3hi[NB * 256 * 256];         // N[b]^T hi [b][j][i]
__device__ __nv_bfloat16 g_W3lo[NB * 256 * 256];

// ---------------- helpers ----------------
__device__ __forceinline__ u32 smem_u32(const void* p) {
    u32 a;
    asm("{ .reg .u64 t; cvta.to.shared.u64 t, %1; cvt.u32.u64 %0, t; }" : "=r"(a) : "l"(p));
    return a;
}
__device__ __forceinline__ void cp16(u32 dst, const void* src) {
    asm volatile("cp.async.cg.shared.global [%0], [%1], 16;" :: "r"(dst), "l"(src) : "memory");
}
__device__ __forceinline__ void cp_commit() { asm volatile("cp.async.commit_group;" ::: "memory"); }
template<int N> __device__ __forceinline__ void cp_wait() {
    asm volatile("cp.async.wait_group %0;" :: "n"(N) : "memory");
}
__device__ __forceinline__ ull pk2(float x, float y) {
    ull r; asm("mov.b64 %0, {%1,%2};" : "=l"(r) : "f"(x), "f"(y)); return r;
}
__device__ __forceinline__ ull fma2(ull a, ull b, ull c) {
    ull d; asm("fma.rn.f32x2 %0, %1, %2, %3;" : "=l"(d) : "l"(a), "l"(b), "l"(c)); return d;
}
__device__ __forceinline__ ull add2(ull a, ull b) {
    ull d; asm("add.rn.f32x2 %0, %1, %2;" : "=l"(d) : "l"(a), "l"(b)); return d;
}
__device__ __forceinline__ void upk2(ull v, float& a, float& b) {
    asm("mov.b64 {%0,%1}, %2;" : "=f"(a), "=f"(b) : "l"(v));
}

// SMEM stage layout (bytes from dynamic base).
// k-chunk 64, row stride 72 bf16 = 144B (LDSM conflict-free: 9r mod 8 distinct).
#define RS 72
#define O_AH 0
#define O_AL 18432
#define O_BH 36864
#define O_BL 73728
#define SZ_ST 110592
#define SMEM_DYN 221184   // 2 stages; epilogue Cs[128][256] f32 (128KB) unioned

// =====================================================================
// wmma bf16 split-3 GEMM, cp.async double-buffered, k-chunk 64.
// C[128-tile x 256] = A @ B^T ; A = pre-split x (hi/lo bf16), B pre-split [n][k].
// mode 0: epilogue computes exp + per-CTA partial S,Z (no C write).
// mode 1: epilogue adds bias, writes C.
// =====================================================================
__global__ void __launch_bounds__(256) mma_gemm(
    const __nv_bfloat16* __restrict__ Ahi, const __nv_bfloat16* __restrict__ Alo, long long sA,
    const __nv_bfloat16* __restrict__ Bhi, const __nv_bfloat16* __restrict__ Blo, long long sB,
    float* __restrict__ C, long long sC,
    const float* __restrict__ bias, int mode)
{
    extern __shared__ unsigned char smem_raw[];
    float* Cs = reinterpret_cast<float*>(smem_raw);
    const u32 sbase = smem_u32(smem_raw);

    const int tid = threadIdx.x;
    const int wid = tid >> 5;
    const int wm = wid >> 2;        // 0..1
    const int wn = wid & 3;         // 0..3
    const int b = blockIdx.y;
    const int l0 = blockIdx.x * 128;

    const __nv_bfloat16* AhiB = Ahi + (size_t)b * sA + (size_t)l0 * 256;
    const __nv_bfloat16* AloB = Alo + (size_t)b * sA + (size_t)l0 * 256;
    const __nv_bfloat16* BhiB = Bhi + (size_t)b * sB;
    const __nv_bfloat16* BloB = Blo + (size_t)b * sB;

    wmma::fragment<wmma::accumulator, 16, 16, 16, float> acc[4][4];
#pragma unroll
    for (int mi = 0; mi < 4; mi++)
#pragma unroll
        for (int ni = 0; ni < 4; ni++) wmma::fill_fragment(acc[mi][ni], 0.0f);

    auto issue_chunk = [&](int it, int st) {
        const int k0 = it * 64;
        const u32 aH = sbase + O_AH + st * SZ_ST;
        const u32 aL = sbase + O_AL + st * SZ_ST;
        const u32 bH = sbase + O_BH + st * SZ_ST;
        const u32 bL = sbase + O_BL + st * SZ_ST;
        // A: 128 rows x 64 k = 1024 16B ops per buffer
#pragma unroll
        for (int i = 0; i < 4; i++) {
            int idx = tid + i * 256;
            int row = idx >> 3, seg = idx & 7;
            size_t go = (size_t)row * 256 + k0 + seg * 8;
            u32 so = (u32)(row * 144 + seg * 16);
            cp16(aH + so, AhiB + go);
            cp16(aL + so, AloB + go);
        }
        // B: 256 rows x 64 k = 2048 16B ops per buffer
#pragma unroll
        for (int i = 0; i < 8; i++) {
            int idx = tid + i * 256;
            int n = idx >> 3, seg = idx & 7;
            size_t go = (size_t)n * 256 + k0 + seg * 8;
            u32 so = (u32)(n * 144 + seg * 16);
            cp16(bH + so, BhiB + go);
            cp16(bL + so, BloB + go);
        }
        cp_commit();
    };

    issue_chunk(0, 0);

    for (int it = 0; it < 4; it++) {
        const int st = it & 1;
        if (it < 3) issue_chunk(it + 1, st ^ 1);
        if (it < 3) cp_wait<1>(); else cp_wait<0>();
        __syncthreads();

        const __nv_bfloat16* Ah = (const __nv_bfloat16*)(smem_raw + O_AH + st * SZ_ST);
        const __nv_bfloat16* Al = (const __nv_bfloat16*)(smem_raw + O_AL + st * SZ_ST);
        const __nv_bfloat16* Bh = (const __nv_bfloat16*)(smem_raw + O_BH + st * SZ_ST);
        const __nv_bfloat16* Bl = (const __nv_bfloat16*)(smem_raw + O_BL + st * SZ_ST);

#pragma unroll
        for (int kk = 0; kk < 4; kk++) {
            wmma::fragment<wmma::matrix_a, 16, 16, 16, __nv_bfloat16, wmma::row_major> ah[4], al[4];
            wmma::fragment<wmma::matrix_b, 16, 16, 16, __nv_bfloat16, wmma::col_major> bh[4], bl[4];
#pragma unroll
            for (int mi = 0; mi < 4; mi++) {
                int r = wm * 64 + mi * 16;
                wmma::load_matrix_sync(ah[mi], Ah + r * RS + kk * 16, RS);
                wmma::load_matrix_sync(al[mi], Al + r * RS + kk * 16, RS);
            }
#pragma unroll
            for (int ni = 0; ni < 4; ni++) {
                int n = wn * 64 + ni * 16;
                wmma::load_matrix_sync(bh[ni], Bh + n * RS + kk * 16, RS);
                wmma::load_matrix_sync(bl[ni], Bl + n * RS + kk * 16, RS);
            }
#pragma unroll
            for (int mi = 0; mi < 4; mi++)
#pragma unroll
                for (int ni = 0; ni < 4; ni++) {
                    wmma::mma_sync(acc[mi][ni], ah[mi], bh[ni], acc[mi][ni]);
                    wmma::mma_sync(acc[mi][ni], ah[mi], bl[ni], acc[mi][ni]);
                    wmma::mma_sync(acc[mi][ni], al[mi], bh[ni], acc[mi][ni]);
                }
        }
        __syncthreads();
    }

    // ---- stage buffers dead; alias Cs[128][256] over them
#pragma unroll
    for (int mi = 0; mi < 4; mi++)
#pragma unroll
        for (int ni = 0; ni < 4; ni++)
            wmma::store_matrix_sync(Cs + (size_t)(wm * 64 + mi * 16) * 256 + wn * 64 + ni * 16,
                                    acc[mi][ni], 256, wmma::mem_row_major);
    __syncthreads();

    if (mode == 1) {
        float* Cb = C + (size_t)b * sC + (size_t)l0 * 256;
#pragma unroll
        for (int i = 0; i < 32; i++) {
            int idx = tid + i * 256;
            int row = idx >> 6, c4 = idx & 63;
            float4 v = *(const float4*)(Cs + (size_t)row * 256 + c4 * 4);
            float4 bb = __ldg((const float4*)(bias + c4 * 4));
            v.x += bb.x; v.y += bb.y; v.z += bb.z; v.w += bb.w;
            *(float4*)(Cb + (size_t)row * 256 + c4 * 4) = v;
        }
        return;
    }

    // ---- mode 0: exp in-place on K half (cols 0..127)
#pragma unroll
    for (int i = 0; i < 16; i++) {
        int idx = tid + i * 256;                  // 4096 float4 slots over 128x128
        int row = idx >> 5, c4 = idx & 31;
        float4 v = *(const float4*)(Cs + (size_t)row * 256 + c4 * 4);
        v.x = expf(v.x); v.y = expf(v.y); v.z = expf(v.z); v.w = expf(v.w);
        *(float4*)(Cs + (size_t)row * 256 + c4 * 4) = v;
    }
    __syncthreads();

    // ---- per-CTA partial S[h][d][e] (fp32, f32x2 packed) + Z[h][d]
    {
        const int h = tid >> 6;
        const int q = tid & 63;
        const int d0 = (q >> 3) * 4;
        const int e0 = (q & 7) * 4;
        ull acc2[4][2];
#pragma unroll
        for (int i = 0; i < 4; i++) { acc2[i][0] = 0ULL; acc2[i][1] = 0ULL; }
        ull z01 = 0ULL, z23 = 0ULL;

#pragma unroll 4
        for (int l = 0; l < 128; l++) {
            float4 ek = *(const float4*)(Cs + (size_t)l * 256 + h * 32 + d0);
            float4 vv = *(const float4*)(Cs + (size_t)l * 256 + 128 + h * 32 + e0);
            ull v01 = pk2(vv.x, vv.y), v23 = pk2(vv.z, vv.w);
            float ea[4] = { ek.x, ek.y, ek.z, ek.w };
#pragma unroll
            for (int i = 0; i < 4; i++) {
                ull ap = pk2(ea[i], ea[i]);
                acc2[i][0] = fma2(ap, v01, acc2[i][0]);
                acc2[i][1] = fma2(ap, v23, acc2[i][1]);
            }
            z01 = add2(z01, pk2(ek.x, ek.y));
            z23 = add2(z23, pk2(ek.z, ek.w));
        }

        float* Sp = g_Sp + (((size_t)(b * 4 + h) * 64 + blockIdx.x) * 1024);
#pragma unroll
        for (int i = 0; i < 4; i++) {
            float s0, s1, s2, s3;
            upk2(acc2[i][0], s0, s1); upk2(acc2[i][1], s2, s3);
            *(float4*)(Sp + (d0 + i) * 32 + e0) = make_float4(s0, s1, s2, s3);
        }
        if (e0 == 0) {
            float z0, z1, z2, z3;
            upk2(z01, z0, z1); upk2(z23, z2, z3);
            float* Zp = g_Zp + ((size_t)(b * 4 + h) * 64 + blockIdx.x) * 32;
            *(float4*)(Zp + d0) = make_float4(z0, z1, z2, z3);
        }
    }
}

// ---------------- split x: fp32 -> bf16 hi/lo ----------------
__global__ void __launch_bounds__(256) split_x(const float* __restrict__ x)
{
    size_t i4 = (size_t)blockIdx.x * 256 + threadIdx.x;   // 8388608 float4 groups
    float4 v = __ldg((const float4*)x + i4);
    float h0 = __bfloat162float(__float2bfloat16(v.x));
    float h1 = __bfloat162float(__float2bfloat16(v.y));
    float h2 = __bfloat162float(__float2bfloat16(v.z));
    float h3 = __bfloat162float(__float2bfloat16(v.w));
    __nv_bfloat162 hi0 = __floats2bfloat162_rn(h0, h1);
    __nv_bfloat162 hi1 = __floats2bfloat162_rn(h2, h3);
    __nv_bfloat162 lo0 = __floats2bfloat162_rn(v.x - h0, v.y - h1);
    __nv_bfloat162 lo1 = __floats2bfloat162_rn(v.z - h2, v.w - h3);
    *(uint2*)(g_Xhi + i4 * 4) = make_uint2(*(u32*)&hi0, *(u32*)&hi1);
    *(uint2*)(g_Xlo + i4 * 4) = make_uint2(*(u32*)&lo0, *(u32*)&lo1);
}

// ---------------- prep: Wkv^T split ----------------
__global__ void prep_w1(const float* __restrict__ Wqkv)
{
    const int n = blockIdx.x, k = threadIdx.x;
    float w = Wqkv[k * QKV_LD + 128 + n];
    float h = __bfloat162float(__float2bfloat16(w));
    g_W1hi[n * 256 + k] = __float2bfloat16(h);
    g_W1lo[n * 256 + k] = __float2bfloat16(w - h);
}

// ---------------- prep: N[b]^T split (tiled transpose) ----------------
__global__ void tsplit()
{
    const int b = blockIdx.z;
    const int i0 = blockIdx.y * 32, j0 = blockIdx.x * 32;
    const int tx = threadIdx.x, ty = threadIdx.y;
    __shared__ float t[32][33];
    const float* Nb = g_N + (size_t)b * 65536;
#pragma unroll
    for (int r = ty; r < 32; r += 8)
        t[r][tx] = Nb[(size_t)(i0 + r) * 256 + j0 + tx];
    __syncthreads();
    __nv_bfloat16* Whi = g_W3hi + (size_t)b * 65536;
    __nv_bfloat16* Wlo = g_W3lo + (size_t)b * 65536;
#pragma unroll
    for (int r = ty; r < 32; r += 8) {
        float v = t[tx][r];
        float h = __bfloat162float(__float2bfloat16(v));
        Whi[(size_t)(j0 + r) * 256 + i0 + tx] = __float2bfloat16(h);
        Wlo[(size_t)(j0 + r) * 256 + i0 + tx] = __float2bfloat16(v - h);
    }
}

// ---------------- small fp32 GEMM (N[b] = scale * Wq @ M[b]) ----------------
__global__ void __launch_bounds__(256) gemm_f32x2(
    const float* __restrict__ A, int lda, long long sA,
    const float* __restrict__ B, int ldb, long long sB,
    float* __restrict__ C, int ldc, long long sC,
    int K, float scale)
{
    const int b = blockIdx.z;
    A += (size_t)b * sA + (size_t)blockIdx.y * 128 * lda;
    B += (size_t)b * sB;
    C += (size_t)b * sC + (size_t)blockIdx.y * 128 * ldc + blockIdx.x * 128;
    const int n0 = blockIdx.x * 128;

    __shared__ float As[16][128];
    __shared__ float Bs[16][128];
    const int tid = threadIdx.x;
    const int tx = tid & 15;
    const int ty = tid >> 4;

    ull acc[8][4];
#pragma unroll
    for (int m = 0; m < 8; m++)
#pragma unroll
        for (int p = 0; p < 4; p++) acc[m][p] = 0ULL;

    for (int k0 = 0; k0 < K; k0 += 16) {
#pragma unroll
        for (int i = 0; i < 2; i++) {
            int f = tid + i * 256;
            int row = f >> 2, c4 = (f & 3) * 4;
            float4 av = *(const float4*)(A + (size_t)row * lda + k0 + c4);
            As[c4 + 0][row] = av.x; As[c4 + 1][row] = av.y;
            As[c4 + 2][row] = av.z; As[c4 + 3][row] = av.w;
        }
#pragma unroll
        for (int i = 0; i < 2; i++) {
            int f = tid + i * 256;
            int row = f >> 5, c = (f & 31) * 4;
            *(float4*)(&Bs[row][c]) = *(const float4*)(B + (size_t)(k0 + row) * ldb + n0 + c);
        }
        __syncthreads();
#pragma unroll
        for (int kk = 0; kk < 16; kk++) {
            float4 a0 = *(const float4*)(&As[kk][ty * 4]);
            float4 a1 = *(const float4*)(&As[kk][64 + ty * 4]);
            float4 b0 = *(const float4*)(&Bs[kk][tx * 4]);
            float4 b1 = *(const float4*)(&Bs[kk][64 + tx * 4]);
            ull bp[4] = { pk2(b0.x, b0.y), pk2(b0.z, b0.w), pk2(b1.x, b1.y), pk2(b1.z, b1.w) };
            float am[8] = { a0.x, a0.y, a0.z, a0.w, a1.x, a1.y, a1.z, a1.w };
#pragma unroll
            for (int m = 0; m < 8; m++) {
                ull ap = pk2(am[m], am[m]);
#pragma unroll
                for (int p = 0; p < 4; p++) acc[m][p] = fma2(ap, bp[p], acc[m][p]);
            }
        }
        __syncthreads();
    }

#pragma unroll
    for (int m = 0; m < 8; m++) {
        int row = (m < 4) ? (ty * 4 + m) : (64 + ty * 4 + m - 4);
        float c0, c1, c2, c3, c4, c5, c6, c7;
        upk2(acc[m][0], c0, c1); upk2(acc[m][1], c2, c3);
        upk2(acc[m][2], c4, c5); upk2(acc[m][3], c6, c7);
        *(float4*)(C + (size_t)row * ldc + tx * 4) =
            make_float4(c0 * scale, c1 * scale, c2 * scale, c3 * scale);
        *(float4*)(C + (size_t)row * ldc + 64 + tx * 4) =
            make_float4(c4 * scale, c5 * scale, c6 * scale, c7 * scale);
    }
}

// ---------------- context = (sum_cta S) / (sum_cta Z) ----------------
__global__ void __launch_bounds__(1024) ctx_kernel()
{
    const int h = blockIdx.x, b = blockIdx.y;
    const int t = threadIdx.x;
    const int d = t >> 5, e = t & 31;
    const float* Sp = g_Sp + (size_t)(b * 4 + h) * 64 * 1024;
    float s = 0.f;
#pragma unroll
    for (int sp = 0; sp < 64; sp++) s += Sp[sp * 1024 + t];
    __shared__ float zs[32];
    if (e == 0) {
        const float* Zp = g_Zp + (size_t)(b * 4 + h) * 64 * 32;
        float zz = 0.f;
#pragma unroll
        for (int sp = 0; sp < 64; sp++) zz += Zp[sp * 32 + d];
        zs[d] = zz;
    }
    __syncthreads();
    g_ctx[(size_t)(b * 4 + h) * 1024 + t] = s / zs[d];
}

// ---------------- M[b] ----------------
__global__ void __launch_bounds__(256) m_kernel(const float* __restrict__ Wout)
{
    const int b = blockIdx.x;
    const int h = blockIdx.y;
    const int j = threadIdx.x;
    __shared__ float cs[1024];
    for (int i = j; i < 1024; i += 256) cs[i] = g_ctx[(size_t)b * 4096 + h * 1024 + i];
    __syncthreads();
    float* Mb = g_M + (size_t)b * HID * ND;
    float w[32];
#pragma unroll
    for (int e = 0; e < 32; e++) w[e] = Wout[(h * 32 + e) * 256 + j];
    for (int d = 0; d < 32; d++) {
        float a = 0.f;
#pragma unroll
        for (int e = 0; e < 32; e++) a += cs[d * 32 + e] * w[e];
        Mb[(h * 32 + d) * 256 + j] = a;
    }
}

// ---------------- launch ----------------
extern "C" void kernel_launch(void* const* d_in, const int* in_sizes, int n_in,
                              void* d_out, int out_size)
{
    const float* x    = (const float*)d_in[0];
    const float* Wqkv = (const float*)d_in[1];
    const float* Wout = (const float*)d_in[2];
    const float* bout = (const float*)d_in[3];
    float* out = (float*)d_out;

    float *Mp, *Np;
    __nv_bfloat16 *xh, *xl, *w1h, *w1l, *w3h, *w3l;
    cudaGetSymbolAddress((void**)&Mp, g_M);
    cudaGetSymbolAddress((void**)&Np, g_N);
    cudaGetSymbolAddress((void**)&xh, g_Xhi);
    cudaGetSymbolAddress((void**)&xl, g_Xlo);
    cudaGetSymbolAddress((void**)&w1h, g_W1hi);
    cudaGetSymbolAddress((void**)&w1l, g_W1lo);
    cudaGetSymbolAddress((void**)&w3h, g_W3hi);
    cudaGetSymbolAddress((void**)&w3l, g_W3lo);

    cudaFuncSetAttribute(mma_gemm, cudaFuncAttributeMaxDynamicSharedMemorySize, SMEM_DYN);

    const float scale = 0.17677669529663687f;
    const long long sX = (long long)NL * ND;

    // 1) split x -> bf16 hi/lo
    split_x<<<32768, 256>>>(x);

    // 2) split Wkv^T
    prep_w1<<<256, 256>>>(Wqkv);

    // 3) kv GEMM + fused exp + partial S,Z (no kv materialization)
    mma_gemm<<<dim3(64, NB), 256, SMEM_DYN>>>(
        xh, xl, sX, w1h, w1l, 0, nullptr, 0, nullptr, 0);

    // 4) context
    ctx_kernel<<<dim3(NH, NB), 1024>>>();

    // 5) M[b]
    m_kernel<<<dim3(NB, NH), 256>>>(Wout);

    // 6) N[b] = scale * Wq @ M[b]
    gemm_f32x2<<<dim3(2, 2, NB), 256>>>(
        Wqkv, QKV_LD, 0, Mp, ND, (long long)HID * ND,
        Np, ND, (long long)ND * ND, HID, scale);

    // 7) transpose+split N[b]
    tsplit<<<dim3(8, 8, NB), dim3(32, 8)>>>();

    // 8) out = x @ N[b] + b_out
    mma_gemm<<<dim3(64, NB), 256, SMEM_DYN>>>(
        xh, xl, sX, w3h, w3l, 65536, out, sX, bout, 1);
}